// round 6
// baseline (speedup 1.0000x reference)
#include <cuda_runtime.h>
#include <cstdint>

#define BATCH 16
#define HH    256
#define WW    256
#define CIN   32
#define COUT  32
#define TAPS  9

#define RPC      8      // output rows per CTA (4 via IMMA + 4 via dp4a)
#define PXC      64     // pixels per CTA
#define NTHREADS 256

// x smem: 10 rows (RPC + 2 halo) x 66 px x 32B, 16B-chunk swizzled
#define XPX   66
#define ROWB  (XPX * 32)

// B fragments in mma.m16n8k32 order: [tap][ntile][lane]
__device__ uint2    g_bfrag[TAPS][4][32];
// dp4a weights: [tap][co][j], j = ci-group of 4, int8 in {-4..4}
__device__ uint32_t g_wpk[TAPS][COUT][8];
__device__ float    g_bias[COUT];

// ---------------------------------------------------------------------------
// Prep: both weight layouts + summed bias. Deterministic every call.
// ---------------------------------------------------------------------------
__global__ void prep_kernel(const float* __restrict__ Wt, const float* __restrict__ bias)
{
    const int kt   = blockIdx.x;        // 9 blocks
    const int t    = threadIdx.x;       // 128 threads
    const int nt   = t >> 5;
    const int lane = t & 31;
    const int g    = lane >> 2;
    const int tg   = lane & 3;
    const int co   = nt * 8 + g;

    // IMMA B-fragment
    {
        uint32_t w0 = 0, w1 = 0;
        #pragma unroll
        for (int j = 0; j < 4; j++) {
            int ci0 = tg * 4 + j;
            int ci1 = 16 + tg * 4 + j;
            int s0 = 0, s1 = 0;
            #pragma unroll
            for (int m = 0; m < 4; m++) {
                float a = Wt[((((size_t)m * TAPS + kt) << 5) + ci0) * 32 + co];
                float b = Wt[((((size_t)m * TAPS + kt) << 5) + ci1) * 32 + co];
                s0 += (a >= 0.0f) ? 1 : -1;
                s1 += (b >= 0.0f) ? 1 : -1;
            }
            w0 |= ((uint32_t)(uint8_t)(int8_t)s0) << (8 * j);
            w1 |= ((uint32_t)(uint8_t)(int8_t)s1) << (8 * j);
        }
        g_bfrag[kt][nt][lane] = make_uint2(w0, w1);
    }

    // dp4a packed weights
    for (int e = t; e < COUT * 8; e += 128) {
        int wco = e >> 3, j = e & 7;
        uint32_t word = 0;
        #pragma unroll
        for (int k = 0; k < 4; k++) {
            int ci = j * 4 + k;
            int s = 0;
            #pragma unroll
            for (int m = 0; m < 4; m++) {
                float w = Wt[((((size_t)m * TAPS + kt) << 5) + ci) * 32 + wco];
                s += (w >= 0.0f) ? 1 : -1;
            }
            word |= ((uint32_t)(uint8_t)(int8_t)s) << (8 * k);
        }
        g_wpk[kt][wco][j] = word;
    }

    if (kt == 0 && t < COUT) {
        float s = 0.0f;
        #pragma unroll
        for (int m = 0; m < 4; m++) s += bias[m * COUT + t];
        g_bias[t] = s;
    }
}

// sign-pack 4 floats -> 4 int8 bytes {+1, -1} via PRMT sign-replicate
__device__ __forceinline__ uint32_t pk4u(uint4 u)
{
    uint32_t s01, s23, m;
    asm("prmt.b32 %0, %1, %2, 0x00FB;" : "=r"(s01) : "r"(u.x), "r"(u.y));
    asm("prmt.b32 %0, %1, %2, 0x00FB;" : "=r"(s23) : "r"(u.z), "r"(u.w));
    asm("prmt.b32 %0, %1, %2, 0x5410;" : "=r"(m)   : "r"(s01), "r"(s23));
    return (m & 0xFEFEFEFEu) ^ 0x01010101u;
}

__device__ __forceinline__ uint32_t smem_u32(const void* p)
{
    uint32_t a;
    asm("{ .reg .u64 t; cvta.to.shared.u64 t, %1; cvt.u32.u64 %0, t; }" : "=r"(a) : "l"(p));
    return a;
}

// ---------------------------------------------------------------------------
// Conv kernel: CTA = 8 rows x 64 px.
//   warps 0-3: IMMA, row = wid      (rows 0-3)
//   warps 4-7: dp4a, row = wid      (rows 4-7)
// SMSP = wid%4 gets 1 IMMA + 1 dp4a warp per CTA -> both pipes busy.
// ---------------------------------------------------------------------------
__global__ void __launch_bounds__(NTHREADS, 2)
conv_kernel(const float* __restrict__ x, float* __restrict__ y)
{
    __shared__ uint32_t sx[10 * ROWB / 4];         // 10 rows x 66 px x 32B
    __shared__ uint2    sbf[TAPS][4][32];          // IMMA B fragments
    __shared__ uint32_t swk[TAPS][COUT][8];        // dp4a weights
    __shared__ float    sbias[COUT];

    const int tid  = threadIdx.x;
    const int lane = tid & 31;
    const int wid  = tid >> 5;
    const int bid  = blockIdx.x;
    const int img  = bid >> 7;
    const int rem  = bid & 127;
    const int h0   = (rem >> 2) * RPC;             // 32 row-tiles
    const int p0   = (rem & 3) * PXC;              // 4 px-tiles

    // ---- stage weights + bias ----
    {
        const uint2* srcA = &g_bfrag[0][0][0];
        uint2*       dstA = &sbf[0][0][0];
        for (int i = tid; i < TAPS * 4 * 32; i += NTHREADS) dstA[i] = srcA[i];
        const uint32_t* srcB = &g_wpk[0][0][0];
        uint32_t*       dstB = &swk[0][0][0];
        for (int i = tid; i < TAPS * COUT * 8; i += NTHREADS) dstB[i] = srcB[i];
    }
    if (tid < COUT) sbias[tid] = g_bias[tid];

    // ---- binarize + pack x: 10 rows x 66 px x 2 chunks = 1320 units ----
    #pragma unroll
    for (int k = 0; k < 6; k++) {
        int i = tid + k * NTHREADS;
        if (i < 10 * XPX * 2) {
            int row = i / (XPX * 2);
            int j   = i - row * (XPX * 2);
            int spx = j >> 1;
            int c   = j & 1;
            int hr  = h0 - 1 + row;
            int px  = p0 + spx - 1;
            uint32_t v0 = 0, v1 = 0, v2 = 0, v3 = 0;
            if (((unsigned)hr < (unsigned)HH) & ((unsigned)px < (unsigned)WW)) {
                const uint4* src = (const uint4*)
                    (x + (((size_t)(img * HH + hr) * WW + px) << 5) + (c << 4));
                uint4 a = src[0], b = src[1], cc = src[2], d = src[3];
                v0 = pk4u(a); v1 = pk4u(b); v2 = pk4u(cc); v3 = pk4u(d);
            }
            uint32_t off = row * ROWB + spx * 32 +
                           (((uint32_t)c ^ ((uint32_t)(spx >> 2) & 1u)) << 4);
            *(uint4*)((char*)sx + off) = make_uint4(v0, v1, v2, v3);
        }
    }
    __syncthreads();

    const int r = wid;                    // output row within tile
    const uint32_t sx_base = smem_u32(sx);

    if (wid < 4) {
        // ===================== IMMA path: row r, 64 px x 32 co =====================
        const int q      = lane >> 3;
        const int px_off = ((q & 1) << 3) + (lane & 7);
        const int chunk  = q >> 1;

        int acc[4][4][4];
        #pragma unroll
        for (int mt = 0; mt < 4; mt++)
            #pragma unroll
            for (int nt = 0; nt < 4; nt++)
                #pragma unroll
                for (int e = 0; e < 4; e++) acc[mt][nt][e] = 0;

        #pragma unroll 1
        for (int kt = 0; kt < TAPS; kt++) {
            const int kh = kt / 3;
            const int kw = kt - kh * 3;

            uint2 b[4];
            #pragma unroll
            for (int nt = 0; nt < 4; nt++) b[nt] = sbf[kt][nt][lane];

            const int xrow = (r + kh) * ROWB;
            #pragma unroll
            for (int mt = 0; mt < 4; mt++) {
                const int spx = mt * 16 + px_off + kw;
                const uint32_t addr = sx_base + xrow + spx * 32 +
                                      (((uint32_t)chunk ^ ((uint32_t)(spx >> 2) & 1u)) << 4);
                uint32_t a0, a1, a2, a3;
                asm volatile("ldmatrix.sync.aligned.m8n8.x4.shared.b16 {%0,%1,%2,%3}, [%4];"
                             : "=r"(a0), "=r"(a1), "=r"(a2), "=r"(a3) : "r"(addr));
                #pragma unroll
                for (int nt = 0; nt < 4; nt++) {
                    asm volatile(
                        "mma.sync.aligned.m16n8k32.row.col.s32.s8.s8.s32 "
                        "{%0,%1,%2,%3}, {%4,%5,%6,%7}, {%8,%9}, {%0,%1,%2,%3};"
                        : "+r"(acc[mt][nt][0]), "+r"(acc[mt][nt][1]),
                          "+r"(acc[mt][nt][2]), "+r"(acc[mt][nt][3])
                        : "r"(a0), "r"(a1), "r"(a2), "r"(a3),
                          "r"(b[nt].x), "r"(b[nt].y));
                }
            }
        }

        const int g2 = lane >> 2;
        const int tg = lane & 3;
        const int hrow = img * HH + h0 + r;
        #pragma unroll
        for (int mt = 0; mt < 4; mt++) {
            const int pxa = p0 + mt * 16 + g2;
            float* dsta = y + (((size_t)hrow * WW + pxa) << 5);
            float* dstb = dsta + (8 << 5);
            #pragma unroll
            for (int nt = 0; nt < 4; nt++) {
                const int co = nt * 8 + 2 * tg;
                const float bz0 = sbias[co], bz1 = sbias[co + 1];
                float2 oa, ob;
                oa.x = (float)acc[mt][nt][0] + bz0;
                oa.y = (float)acc[mt][nt][1] + bz1;
                ob.x = (float)acc[mt][nt][2] + bz0;
                ob.y = (float)acc[mt][nt][3] + bz1;
                *(float2*)(dsta + co) = oa;
                *(float2*)(dstb + co) = ob;
            }
        }
    } else {
        // ===================== dp4a path: row r, 64 px (2 passes) =====================
        const int hrow = img * HH + h0 + r;

        #pragma unroll 1
        for (int p = 0; p < 2; p++) {
            const int spx0 = p * 32 + lane;   // tile pixel index (unpadded base)

            int acc[COUT];
            #pragma unroll
            for (int co = 0; co < COUT; co++) acc[co] = 0;

            #pragma unroll 1
            for (int tap = 0; tap < TAPS; tap++) {
                const int kh = tap / 3;
                const int kw = tap - kh * 3;
                const int spx = spx0 + kw;                   // padded coords
                const char* base = (const char*)sx + (r + kh) * ROWB + spx * 32;
                const uint32_t cs = (((uint32_t)(spx >> 2)) & 1u) << 4;
                const int4 x0 = *(const int4*)(base + (0u  ^ cs));
                const int4 x1 = *(const int4*)(base + (16u ^ cs));

                const int4* wp = (const int4*)&swk[tap][0][0];
                #pragma unroll
                for (int co = 0; co < COUT; co++) {
                    const int4 w0 = wp[co * 2 + 0];   // broadcast (lane-uniform)
                    const int4 w1 = wp[co * 2 + 1];
                    int s = acc[co];
                    s = __dp4a(x0.x, w0.x, s); s = __dp4a(x0.y, w0.y, s);
                    s = __dp4a(x0.z, w0.z, s); s = __dp4a(x0.w, w0.w, s);
                    s = __dp4a(x1.x, w1.x, s); s = __dp4a(x1.y, w1.y, s);
                    s = __dp4a(x1.z, w1.z, s); s = __dp4a(x1.w, w1.w, s);
                    acc[co] = s;
                }
            }

            const int pxg = p0 + p * 32 + lane;
            float4* dst = (float4*)(y + (((size_t)hrow * WW + pxg) << 5));
            #pragma unroll
            for (int q = 0; q < 8; q++) {
                float4 o;
                o.x = (float)acc[q * 4 + 0] + sbias[q * 4 + 0];
                o.y = (float)acc[q * 4 + 1] + sbias[q * 4 + 1];
                o.z = (float)acc[q * 4 + 2] + sbias[q * 4 + 2];
                o.w = (float)acc[q * 4 + 3] + sbias[q * 4 + 3];
                dst[q] = o;
            }
        }
    }
}

extern "C" void kernel_launch(void* const* d_in, const int* in_sizes, int n_in,
                              void* d_out, int out_size)
{
    const float* x = (const float*)d_in[0];   // [16,256,256,32]
    const float* W = (const float*)d_in[1];   // [4,3,3,32,32]
    const float* b = (const float*)d_in[2];   // [4,32]
    float* y = (float*)d_out;                 // [16,256,256,32]

    prep_kernel<<<TAPS, 128>>>(W, b);
    conv_kernel<<<BATCH * (HH / RPC) * (WW / PXC), NTHREADS>>>(x, y);
}

// round 7
// speedup vs baseline: 1.1559x; 1.1559x over previous
#include <cuda_runtime.h>
#include <cstdint>

#define BATCH 16
#define HH    256
#define WW    256
#define CIN   32
#define COUT  32
#define TAPS  9

#define RPC      8      // output rows per CTA (4 IMMA + 4 dp4a)
#define PXC      64     // pixels per CTA
#define NTHREADS 256

// x smem: 10 rows (RPC + 2 halo) x 66 px x 32B, 16B-chunk swizzled
#define XPX   66
#define ROWB  (XPX * 32)

// B fragments in mma.m16n8k32 order: [tap][ntile][lane]
__device__ uint2    g_bfrag[TAPS][4][32];
// dp4a weights: [tap][co][j], j = ci-group of 4, int8 in {-4..4}
__device__ uint32_t g_wpk[TAPS][COUT][8];
__device__ float    g_bias[COUT];

// ---------------------------------------------------------------------------
// Prep: both weight layouts + summed bias. Deterministic every call.
// ---------------------------------------------------------------------------
__global__ void prep_kernel(const float* __restrict__ Wt, const float* __restrict__ bias)
{
    const int kt   = blockIdx.x;        // 9 blocks
    const int t    = threadIdx.x;       // 128 threads
    const int nt   = t >> 5;
    const int lane = t & 31;
    const int g    = lane >> 2;
    const int tg   = lane & 3;
    const int co   = nt * 8 + g;

    // IMMA B-fragment
    {
        uint32_t w0 = 0, w1 = 0;
        #pragma unroll
        for (int j = 0; j < 4; j++) {
            int ci0 = tg * 4 + j;
            int ci1 = 16 + tg * 4 + j;
            int s0 = 0, s1 = 0;
            #pragma unroll
            for (int m = 0; m < 4; m++) {
                float a = Wt[((((size_t)m * TAPS + kt) << 5) + ci0) * 32 + co];
                float b = Wt[((((size_t)m * TAPS + kt) << 5) + ci1) * 32 + co];
                s0 += (a >= 0.0f) ? 1 : -1;
                s1 += (b >= 0.0f) ? 1 : -1;
            }
            w0 |= ((uint32_t)(uint8_t)(int8_t)s0) << (8 * j);
            w1 |= ((uint32_t)(uint8_t)(int8_t)s1) << (8 * j);
        }
        g_bfrag[kt][nt][lane] = make_uint2(w0, w1);
    }

    // dp4a packed weights
    for (int e = t; e < COUT * 8; e += 128) {
        int wco = e >> 3, j = e & 7;
        uint32_t word = 0;
        #pragma unroll
        for (int k = 0; k < 4; k++) {
            int ci = j * 4 + k;
            int s = 0;
            #pragma unroll
            for (int m = 0; m < 4; m++) {
                float w = Wt[((((size_t)m * TAPS + kt) << 5) + ci) * 32 + wco];
                s += (w >= 0.0f) ? 1 : -1;
            }
            word |= ((uint32_t)(uint8_t)(int8_t)s) << (8 * k);
        }
        g_wpk[kt][wco][j] = word;
    }

    if (kt == 0 && t < COUT) {
        float s = 0.0f;
        #pragma unroll
        for (int m = 0; m < 4; m++) s += bias[m * COUT + t];
        g_bias[t] = s;
    }
}

// sign-pack 4 floats -> 4 int8 bytes {+1, -1} via PRMT sign-replicate
__device__ __forceinline__ uint32_t pk4u(uint4 u)
{
    uint32_t s01, s23, m;
    asm("prmt.b32 %0, %1, %2, 0x00FB;" : "=r"(s01) : "r"(u.x), "r"(u.y));
    asm("prmt.b32 %0, %1, %2, 0x00FB;" : "=r"(s23) : "r"(u.z), "r"(u.w));
    asm("prmt.b32 %0, %1, %2, 0x5410;" : "=r"(m)   : "r"(s01), "r"(s23));
    return (m & 0xFEFEFEFEu) ^ 0x01010101u;
}

__device__ __forceinline__ uint32_t smem_u32(const void* p)
{
    uint32_t a;
    asm("{ .reg .u64 t; cvta.to.shared.u64 t, %1; cvt.u32.u64 %0, t; }" : "=r"(a) : "l"(p));
    return a;
}

// ---------------------------------------------------------------------------
// Conv kernel: CTA = 8 rows x 64 px.
//   warps 0-3: IMMA (tensor pipe), row = wid
//   warps 4-7: dp4a (fma pipe),    row = wid, lane = cout
// Each SMSP hosts 1 IMMA + 1 dp4a warp per CTA -> both pipes busy.
// ---------------------------------------------------------------------------
__global__ void __launch_bounds__(NTHREADS, 2)
conv_kernel(const float* __restrict__ x, float* __restrict__ y)
{
    __shared__ uint32_t sx[10 * ROWB / 4];         // 10 rows x 66 px x 32B
    __shared__ uint2    sbf[TAPS][4][32];          // IMMA B fragments
    __shared__ uint32_t swk[TAPS][COUT][8];        // dp4a weights
    __shared__ float    sbias[COUT];

    const int tid  = threadIdx.x;
    const int lane = tid & 31;
    const int wid  = tid >> 5;
    const int bid  = blockIdx.x;
    const int img  = bid >> 7;
    const int rem  = bid & 127;
    const int h0   = (rem >> 2) * RPC;             // 32 row-tiles
    const int p0   = (rem & 3) * PXC;              // 4 px-tiles

    // ---- stage weights + bias ----
    {
        const uint2* srcA = &g_bfrag[0][0][0];
        uint2*       dstA = &sbf[0][0][0];
        for (int i = tid; i < TAPS * 4 * 32; i += NTHREADS) dstA[i] = srcA[i];
        const uint32_t* srcB = &g_wpk[0][0][0];
        uint32_t*       dstB = &swk[0][0][0];
        for (int i = tid; i < TAPS * COUT * 8; i += NTHREADS) dstB[i] = srcB[i];
    }
    if (tid < COUT) sbias[tid] = g_bias[tid];

    // ---- binarize + pack x: 10 rows x 66 px x 2 chunks = 1320 units ----
    #pragma unroll
    for (int k = 0; k < 6; k++) {
        int i = tid + k * NTHREADS;
        if (i < 10 * XPX * 2) {
            int row = i / (XPX * 2);
            int j   = i - row * (XPX * 2);
            int spx = j >> 1;
            int c   = j & 1;
            int hr  = h0 - 1 + row;
            int px  = p0 + spx - 1;
            uint32_t v0 = 0, v1 = 0, v2 = 0, v3 = 0;
            if (((unsigned)hr < (unsigned)HH) & ((unsigned)px < (unsigned)WW)) {
                const uint4* src = (const uint4*)
                    (x + (((size_t)(img * HH + hr) * WW + px) << 5) + (c << 4));
                uint4 a = src[0], b = src[1], cc = src[2], d = src[3];
                v0 = pk4u(a); v1 = pk4u(b); v2 = pk4u(cc); v3 = pk4u(d);
            }
            uint32_t off = row * ROWB + spx * 32 +
                           (((uint32_t)c ^ ((uint32_t)(spx >> 2) & 1u)) << 4);
            *(uint4*)((char*)sx + off) = make_uint4(v0, v1, v2, v3);
        }
    }
    __syncthreads();

    const int r = wid;                    // output row within tile (per warp)
    const uint32_t sx_base = smem_u32(sx);

    if (wid < 4) {
        // ===================== IMMA path: row r, 64 px x 32 co =====================
        const int q      = lane >> 3;
        const int px_off = ((q & 1) << 3) + (lane & 7);
        const int chunk  = q >> 1;

        int acc[4][4][4];
        #pragma unroll
        for (int mt = 0; mt < 4; mt++)
            #pragma unroll
            for (int nt = 0; nt < 4; nt++)
                #pragma unroll
                for (int e = 0; e < 4; e++) acc[mt][nt][e] = 0;

        #pragma unroll 1
        for (int kt = 0; kt < TAPS; kt++) {
            const int kh = kt / 3;
            const int kw = kt - kh * 3;

            uint2 b[4];
            #pragma unroll
            for (int nt = 0; nt < 4; nt++) b[nt] = sbf[kt][nt][lane];

            const int xrow = (r + kh) * ROWB;
            #pragma unroll
            for (int mt = 0; mt < 4; mt++) {
                const int spx = mt * 16 + px_off + kw;
                const uint32_t addr = sx_base + xrow + spx * 32 +
                                      (((uint32_t)chunk ^ ((uint32_t)(spx >> 2) & 1u)) << 4);
                uint32_t a0, a1, a2, a3;
                asm volatile("ldmatrix.sync.aligned.m8n8.x4.shared.b16 {%0,%1,%2,%3}, [%4];"
                             : "=r"(a0), "=r"(a1), "=r"(a2), "=r"(a3) : "r"(addr));
                #pragma unroll
                for (int nt = 0; nt < 4; nt++) {
                    asm volatile(
                        "mma.sync.aligned.m16n8k32.row.col.s32.s8.s8.s32 "
                        "{%0,%1,%2,%3}, {%4,%5,%6,%7}, {%8,%9}, {%0,%1,%2,%3};"
                        : "+r"(acc[mt][nt][0]), "+r"(acc[mt][nt][1]),
                          "+r"(acc[mt][nt][2]), "+r"(acc[mt][nt][3])
                        : "r"(a0), "r"(a1), "r"(a2), "r"(a3),
                          "r"(b[nt].x), "r"(b[nt].y));
                }
            }
        }

        const int g2 = lane >> 2;
        const int tg = lane & 3;
        const int hrow = img * HH + h0 + r;
        #pragma unroll
        for (int mt = 0; mt < 4; mt++) {
            const int pxa = p0 + mt * 16 + g2;
            float* dsta = y + (((size_t)hrow * WW + pxa) << 5);
            float* dstb = dsta + (8 << 5);
            #pragma unroll
            for (int nt = 0; nt < 4; nt++) {
                const int co = nt * 8 + 2 * tg;
                const float bz0 = sbias[co], bz1 = sbias[co + 1];
                float2 oa, ob;
                oa.x = (float)acc[mt][nt][0] + bz0;
                oa.y = (float)acc[mt][nt][1] + bz1;
                ob.x = (float)acc[mt][nt][2] + bz0;
                ob.y = (float)acc[mt][nt][3] + bz1;
                *(float2*)(dsta + co) = oa;
                *(float2*)(dstb + co) = ob;
            }
        }
    } else {
        // ===================== dp4a path: row r, 64 px, lane = cout =====================
        // Preload this lane's 72 weight words into registers (one-time, 18 LDS.128).
        uint32_t wr[TAPS][8];
        #pragma unroll
        for (int tap = 0; tap < TAPS; tap++) {
            const uint4* wp = (const uint4*)&swk[tap][lane][0];
            uint4 a = wp[0], b = wp[1];
            wr[tap][0] = a.x; wr[tap][1] = a.y; wr[tap][2] = a.z; wr[tap][3] = a.w;
            wr[tap][4] = b.x; wr[tap][5] = b.y; wr[tap][6] = b.z; wr[tap][7] = b.w;
        }
        const float biasv = sbias[lane];
        const int hrow = img * HH + h0 + r;
        float* const orow = y + (((size_t)hrow * WW + p0) << 5) + lane;

        #pragma unroll 2
        for (int px = 0; px < PXC; px++) {
            int acc[3] = {0, 0, 0};
            #pragma unroll
            for (int kh = 0; kh < 3; kh++) {
                const char* rbase = (const char*)sx + (r + kh) * ROWB;
                #pragma unroll
                for (int kw = 0; kw < 3; kw++) {
                    const int tap = kh * 3 + kw;
                    const int spx = px + kw;                 // padded coords
                    const char* base = rbase + spx * 32;
                    const uint32_t cs = (((uint32_t)(spx >> 2)) & 1u) << 4;
                    // lane-uniform broadcast loads (1 crossbar phase each)
                    const int4 x0 = *(const int4*)(base + (0u  ^ cs));
                    const int4 x1 = *(const int4*)(base + (16u ^ cs));
                    int s = acc[kh];
                    s = __dp4a(x0.x, (int)wr[tap][0], s);
                    s = __dp4a(x0.y, (int)wr[tap][1], s);
                    s = __dp4a(x0.z, (int)wr[tap][2], s);
                    s = __dp4a(x0.w, (int)wr[tap][3], s);
                    s = __dp4a(x1.x, (int)wr[tap][4], s);
                    s = __dp4a(x1.y, (int)wr[tap][5], s);
                    s = __dp4a(x1.z, (int)wr[tap][6], s);
                    s = __dp4a(x1.w, (int)wr[tap][7], s);
                    acc[kh] = s;
                }
            }
            const int sum = acc[0] + acc[1] + acc[2];
            orow[px << 5] = (float)sum + biasv;
        }
    }
}

extern "C" void kernel_launch(void* const* d_in, const int* in_sizes, int n_in,
                              void* d_out, int out_size)
{
    const float* x = (const float*)d_in[0];   // [16,256,256,32]
    const float* W = (const float*)d_in[1];   // [4,3,3,32,32]
    const float* b = (const float*)d_in[2];   // [4,32]
    float* y = (float*)d_out;                 // [16,256,256,32]

    prep_kernel<<<TAPS, 128>>>(W, b);
    conv_kernel<<<BATCH * (HH / RPC) * (WW / PXC), NTHREADS>>>(x, y);
}